// round 14
// baseline (speedup 1.0000x reference)
#include <cuda_runtime.h>

// ---------------- problem constants (fixed shapes) ----------------
#define BB   4
#define CC   64
#define HH   288
#define WW   432
#define PW   72            // W / TEM
#define TEM_ 6
#define VV   (HH*WW)       // 124416
#define RN   ((HH-1)*PW)   // 20664  vertical edges per phase
#define CN   (HH*(PW-1))   // 20448  horizontal edges per phase
#define XN   (HH*PW)       // 20736  cross edges per phase pair
#define PB   (RN+CN)       // 41112  weight-layout per-phase block
#define EE   (6*RN+6*CN+5*XN) // 350352 total edges
#define NOUT (VV-1)        // 124415 output entries per batch
#define SENT 0xFFFFFFFFFFFFFFFFULL
#define NROUNDS 18

#define NBLK 32                    // blocks per batch (128 total <= 148 SMs -> co-resident)
#define BTH  1024
#define NW   (BTH/32)
#define TPB  (NBLK*BTH)            // threads per batch
#define SEG  ((EE + NBLK - 1) / NBLK)  // compaction segment per block

#define WQ   108                   // column quads per row
#define WSY  2                     // row-strips per block
#define WBX  36                    // blocks per batch (72 strips / 2)
#define WTT  (WQ*WSY)              // 216 threads per weight block

typedef unsigned long long u64;

// ---------------- scratch (device globals; no allocation) ----------------
__device__ u64 g_keys[BB*EE];          // weight-layout key at position e; low 32 = e
__device__ u64 g_minkey[2][BB*VV];     // ping-pong per-round min-key buffers
__device__ u64 g_euv[BB*EE];           // current (cu,cv) of surviving edge e
__device__ int g_comp[BB*VV];
__device__ int g_parent[BB*VV];        // round 0 only
__device__ unsigned char g_mask[BB*EE];
__device__ ulonglong2 g_elist[2][BB*EE];  // {key, (cv<<32)|cu}
__device__ int g_ecnt[NROUNDS][BB];
__device__ int g_rcnt[NROUNDS][BB];
__device__ int g_roots[3][BB*VV];      // 3-deep rotation: need r-2, r-1, r
__device__ unsigned g_barcnt[BB];
__device__ int g_bcnt[BB*NBLK];

// endpoints of edge e in INDEX layout: [rows x6 | cols x6 | cross x5]
__device__ __forceinline__ void edge_uv(int e, int& u, int& v) {
    if (e < 6*RN) {
        int i = e / RN; int j = e - i*RN;
        int r = j / PW;  int c = j - r*PW;
        u = r*WW + i*PW + c; v = u + WW;
    } else if (e < 6*RN + 6*CN) {
        int t = e - 6*RN;
        int i = t / CN; int j = t - i*CN;
        int r = j / (PW-1); int c = j - r*(PW-1);
        u = r*WW + i*PW + c; v = u + 1;
    } else {
        int t = e - 6*RN - 6*CN;
        int i = t / XN; int j = t - i*XN;
        int r = j / PW; int c = j - r*PW;
        u = r*WW + i*PW + c; v = u + PW;
    }
}

__device__ __forceinline__ int chase_root(const int* par, int c) {
    for (int it = 0; it < VV + 2; it++) {
        int p = par[c];
        if (p == c) break;
        int gp = par[p];
        if (gp == c) { c = (c < p) ? c : p; break; }  // 2-cycle: min of pair
        c = p;
    }
    return c;
}

// chase via minkey-derived parents: parent(c) = partner(minkey[c]) or c if SENT
__device__ __forceinline__ int chase_mk(const u64* mk, const u64* euv, int c) {
    u64 m = mk[c];
    for (int it = 0; it < VV + 2; it++) {
        if (m == SENT) return c;                       // c is root
        u64 uv = euv[(unsigned)(m & 0xFFFFFFFFu)];
        int a = (int)(unsigned)(uv & 0xFFFFFFFFu);
        int d = (int)(unsigned)(uv >> 32);
        int p = (a == c) ? d : a;                      // parent(c)
        u64 m2 = mk[p];
        int gp = p;
        if (m2 != SENT) {
            u64 uv2 = euv[(unsigned)(m2 & 0xFFFFFFFFu)];
            int a2 = (int)(unsigned)(uv2 & 0xFFFFFFFFu);
            int d2 = (int)(unsigned)(uv2 >> 32);
            gp = (a2 == p) ? d2 : a2;
        }
        if (gp == c) return (c < p) ? c : p;           // 2-cycle: min of pair
        c = p; m = m2;
    }
    return c;
}

// per-batch grid barrier (all NBLK blocks of batch b co-resident by construction)
__device__ __forceinline__ void batch_barrier(int b, unsigned& target) {
    __syncthreads();
    if (threadIdx.x == 0) {
        __threadfence();
        atomicAdd(&g_barcnt[b], 1u);
        target += NBLK;
        volatile unsigned* p = &g_barcnt[b];
        while (*p < target) { __nanosleep(64); }
        __threadfence();
    }
    __syncthreads();
}

// warp-aggregated append (1 slot per pred); all 32 lanes must call
__device__ __forceinline__ int warp_reserve(int* ctr, bool pred) {
    unsigned ball = __ballot_sync(0xffffffffu, pred);
    int lane = threadIdx.x & 31;
    int total = __popc(ball);
    int base = 0;
    if (lane == 0 && total) base = atomicAdd(ctr, total);
    base = __shfl_sync(0xffffffffu, base, 0);
    return base + __popc(ball & ((1u << lane) - 1u));
}

// warp-aggregated multi-append (cnt in 0..3); all 32 lanes must call
__device__ __forceinline__ int warp_reserve_n(int* ctr, int cnt) {
    int lane = threadIdx.x & 31;
    int inc = cnt;
    #pragma unroll
    for (int off = 1; off < 32; off <<= 1) {
        int y = __shfl_up_sync(0xffffffffu, inc, off);
        if (lane >= off) inc += y;
    }
    int total = __shfl_sync(0xffffffffu, inc, 31);
    int base = 0;
    if (lane == 0 && total) base = atomicAdd(ctr, total);
    base = __shfl_sync(0xffffffffu, base, 0);
    return base + inc - cnt;
}

__device__ __forceinline__ u64 pack_key(float w, int e) {
    return ((u64)__float_as_uint(w) << 32) | (unsigned)e;
}

// ---------------- weights: 4x4 register strip per thread ----------------
__global__ void __launch_bounds__(WTT) weight_kernel(const float* __restrict__ fm) {
    int b  = blockIdx.y;
    int q  = threadIdx.x;                 // column quad 0..107
    int sy = threadIdx.y;                 // strip-in-block 0..1
    int r0 = (blockIdx.x * WSY + sy) * 4; // strip base row
    int c  = q * 4;
    int ph = c / PW;
    int cc = c - ph * PW;

    bool hasX  = (ph < TEM_ - 1);
    bool hasH3 = (cc < PW - 4);
    bool hasR4 = (r0 + 4) < HH;           // halo row exists

    float sv[4][4] = {}, sh[4][4] = {}, sx[4][4] = {};

    const float* pb = fm + (size_t)b * CC * VV + (size_t)r0 * WW + c;

    for (int ch = 0; ch < CC; ch++) {
        const float* p = pb + (size_t)ch * VV;
        float4 x[5];
        #pragma unroll
        for (int i = 0; i < 4; i++) x[i] = *reinterpret_cast<const float4*>(p + i*WW);
        x[4] = hasR4 ? *reinterpret_cast<const float4*>(p + 4*WW) : make_float4(0.f,0.f,0.f,0.f);

        #pragma unroll
        for (int i = 0; i < 4; i++) {
            {   // vertical: x[i] - x[i+1]  (row r0+3 guarded at write)
                float t0 = x[i].x - x[i+1].x, t1 = x[i].y - x[i+1].y;
                float t2 = x[i].z - x[i+1].z, t3 = x[i].w - x[i+1].w;
                sv[i][0] += t0*t0; sv[i][1] += t1*t1; sv[i][2] += t2*t2; sv[i][3] += t3*t3;
            }
            {   // horizontal
                float xr = hasH3 ? __ldg(p + i*WW + 4) : 0.f;
                float t0 = x[i].x - x[i].y, t1 = x[i].y - x[i].z;
                float t2 = x[i].z - x[i].w, t3 = x[i].w - xr;
                sh[i][0] += t0*t0; sh[i][1] += t1*t1; sh[i][2] += t2*t2; sh[i][3] += t3*t3;
            }
            if (hasX) {
                float4 d = *reinterpret_cast<const float4*>(p + i*WW + PW);
                float t0 = x[i].x - d.x, t1 = x[i].y - d.y;
                float t2 = x[i].z - d.z, t3 = x[i].w - d.w;
                sx[i][0] += t0*t0; sx[i][1] += t1*t1; sx[i][2] += t2*t2; sx[i][3] += t3*t3;
            }
        }
    }

    u64* kb = g_keys + (size_t)b * EE;
    #pragma unroll
    for (int i = 0; i < 4; i++) {
        int row = r0 + i;
        if (row < HH - 1) {
            int e = ph*PB + row*PW + cc;
            kb[e+0] = pack_key(sv[i][0], e+0); kb[e+1] = pack_key(sv[i][1], e+1);
            kb[e+2] = pack_key(sv[i][2], e+2); kb[e+3] = pack_key(sv[i][3], e+3);
        }
        {
            int e = ph*PB + RN + row*(PW-1) + cc;
            kb[e+0] = pack_key(sh[i][0], e+0); kb[e+1] = pack_key(sh[i][1], e+1);
            kb[e+2] = pack_key(sh[i][2], e+2);
            if (hasH3) kb[e+3] = pack_key(sh[i][3], e+3);
        }
        if (hasX) {
            int e = 6*PB + ph*XN + row*PW + cc;
            kb[e+0] = pack_key(sx[i][0], e+0); kb[e+1] = pack_key(sx[i][1], e+1);
            kb[e+2] = pack_key(sx[i][2], e+2); kb[e+3] = pack_key(sx[i][3], e+3);
        }
    }

    // ---- fused scratch init (grid-stride over all weight threads) ----
    const int TOT = BB * WBX * WTT;   // 31104
    int gid = (b * WBX + blockIdx.x) * WTT + sy * WQ + q;
    {   // both minkey buffers: 2*BB*VV u64 = 497664 ulonglong2
        ulonglong2 s2 = make_ulonglong2(SENT, SENT);
        ulonglong2* mk = reinterpret_cast<ulonglong2*>(&g_minkey[0][0]);
        for (int i = gid; i < (2*BB*VV)/2; i += TOT) mk[i] = s2;
    }
    {   // mask zero
        u64* m8 = reinterpret_cast<u64*>(g_mask);
        for (int i = gid; i < (BB*EE)/8; i += TOT) m8[i] = 0ULL;
    }
    if (gid < NROUNDS*BB) { (&g_ecnt[0][0])[gid] = 0; (&g_rcnt[0][0])[gid] = 0; }
    if (gid < BB)         g_barcnt[gid] = 0;
    if (gid < BB*NBLK)    g_bcnt[gid] = 0;
}

// ---------------- persistent Boruvka + compaction (R11, proven) ----------------
__global__ void __launch_bounds__(BTH, 1) boruvka_kernel(float* __restrict__ out, int stride) {
    int b   = blockIdx.y;
    int tid = threadIdx.x;
    int gt  = blockIdx.x * BTH + tid;
    unsigned bar_target = 0;

    u64* keys   = g_keys + (size_t)b*EE;
    u64* euv    = g_euv  + (size_t)b*EE;
    int* parent = g_parent + b*VV;
    int* comp   = g_comp + b*VV;
    unsigned char* mask = g_mask + (size_t)b*EE;

    // ===== round 0: per-vertex gather over <=6 incident edges (INDEX layout ids) =====
    for (int x = gt; x < VV; x += TPB) {
        int r = x / WW; int col = x - r*WW; int ph = col / PW; int c = col - ph*PW;
        u64 best = SENT;
        u64 k;
        int ev = ph*RN + r*PW + c;                    // vertical
        if (r < HH-1) { k = keys[ev];        if (k < best) best = k; }
        if (r > 0)    { k = keys[ev - PW];   if (k < best) best = k; }
        int eh = 6*RN + ph*CN + r*(PW-1) + c;         // horizontal
        if (c < PW-1) { k = keys[eh];        if (k < best) best = k; }
        if (c > 0)    { k = keys[eh - 1];    if (k < best) best = k; }
        int ex = 6*RN + 6*CN + ph*XN + r*PW + c;      // cross
        if (ph < TEM_-1) { k = keys[ex];      if (k < best) best = k; }
        if (ph > 0)      { k = keys[ex - XN]; if (k < best) best = k; }

        int e = (int)(unsigned)(best & 0xFFFFFFFFu);
        mask[e] = 1;
        int u, v; edge_uv(e, u, v);
        parent[x] = (u == x) ? v : u;
    }
    batch_barrier(b, bar_target);

    // round 0: chase over all V, collect roots -> slot 0
    {
        const int nn = ((VV + TPB - 1) / TPB) * TPB;
        for (int x = gt; x < nn; x += TPB) {
            bool isroot = false;
            if (x < VV) {
                int c = chase_root(parent, x);
                comp[x] = c;
                isroot = (c == x);
            }
            int pos = warp_reserve(&g_rcnt[0][b], isroot);
            if (isroot) g_roots[0][b*VV + pos] = x;
        }
    }
    batch_barrier(b, bar_target);

    // ===== rounds 1..17: [edge | barrier | fused select+chase | barrier] =====
    for (int r = 1; r < NROUNDS; r++) {
        u64* mkc = g_minkey[r & 1] + b*VV;              // written this round

        // ---- edge phase ----
        if (r == 1) {
            // vertex-centric: each vertex reduces its <=6 incident edges, owns 3 appends
            ulonglong2* dst = g_elist[1] + (size_t)b*EE;
            const int nn = ((VV + TPB - 1) / TPB) * TPB;
            for (int x = gt; x < nn; x += TPB) {
                int cnt = 0;
                u64 ak[3], auv[3];
                u64 best = SENT;
                if (x < VV) {
                    int cx = comp[x];
                    int rr = x / WW; int col = x - rr*WW; int ph = col / PW; int c = col - ph*PW;
                    int ev = ph*RN + rr*PW + c;
                    int eh = 6*RN + ph*CN + rr*(PW-1) + c;
                    int ex = 6*RN + 6*CN + ph*XN + rr*PW + c;
                    if (rr < HH-1) {
                        int cn = comp[x + WW];
                        if (cn != cx) {
                            u64 k = keys[ev]; if (k < best) best = k;
                            u64 uv = ((u64)(unsigned)cn << 32) | (unsigned)cx;
                            euv[ev] = uv; ak[cnt] = k; auv[cnt] = uv; cnt++;
                        }
                    }
                    if (rr > 0) {
                        int cn = comp[x - WW];
                        if (cn != cx) { u64 k = keys[ev - PW]; if (k < best) best = k; }
                    }
                    if (c < PW-1) {
                        int cn = comp[x + 1];
                        if (cn != cx) {
                            u64 k = keys[eh]; if (k < best) best = k;
                            u64 uv = ((u64)(unsigned)cn << 32) | (unsigned)cx;
                            euv[eh] = uv; ak[cnt] = k; auv[cnt] = uv; cnt++;
                        }
                    }
                    if (c > 0) {
                        int cn = comp[x - 1];
                        if (cn != cx) { u64 k = keys[eh - 1]; if (k < best) best = k; }
                    }
                    if (ph < TEM_-1) {
                        int cn = comp[x + PW];
                        if (cn != cx) {
                            u64 k = keys[ex]; if (k < best) best = k;
                            u64 uv = ((u64)(unsigned)cn << 32) | (unsigned)cx;
                            euv[ex] = uv; ak[cnt] = k; auv[cnt] = uv; cnt++;
                        }
                    }
                    if (ph > 0) {
                        int cn = comp[x - PW];
                        if (cn != cx) { u64 k = keys[ex - XN]; if (k < best) best = k; }
                    }
                    if (best != SENT) atomicMin(&mkc[cx], best);
                }
                int pos = warp_reserve_n(&g_ecnt[1][b], cnt);
                #pragma unroll
                for (int j = 0; j < 3; j++)
                    if (j < cnt) dst[pos + j] = make_ulonglong2(ak[j], auv[j]);
            }
        } else {
            int n = g_ecnt[r-1][b];
            const ulonglong2* src = g_elist[(r-1) & 1] + (size_t)b*EE;
            ulonglong2* dst = g_elist[r & 1] + (size_t)b*EE;
            int nn = ((n + TPB - 1) / TPB) * TPB;
            for (int i = gt; i < nn; i += TPB) {
                bool pred = false; u64 k = 0, uvp = 0;
                if (i < n) {
                    ulonglong2 ed = src[i];
                    int u = (int)(unsigned)(ed.y & 0xFFFFFFFFu);
                    int v = (int)(unsigned)(ed.y >> 32);
                    int cu = comp[u], cv = comp[v];
                    if (cu != cv) {
                        pred = true;
                        k = ed.x;
                        atomicMin(&mkc[cu], k);
                        atomicMin(&mkc[cv], k);
                        uvp = ((u64)(unsigned)cv << 32) | (unsigned)cu;
                        euv[(unsigned)(k & 0xFFFFFFFFu)] = uvp;
                    }
                }
                int pos = warp_reserve(&g_ecnt[r][b], pred);
                if (pred) dst[pos] = make_ulonglong2(k, uvp);
            }
        }
        batch_barrier(b, bar_target);

        if (g_ecnt[r][b] == 0) break;   // fully merged -> mask complete

        // ---- fused select + chase over roots[r-1]; reset prev minkey over roots[r-2] ----
        {
            int n = g_rcnt[r-1][b];
            const int* rl = g_roots[(r-1) % 3] + b*VV;
            int* wl = g_roots[r % 3] + b*VV;
            int nn = ((n + TPB - 1) / TPB) * TPB;
            for (int i = gt; i < nn; i += TPB) {
                bool isroot = false;
                int x = 0;
                if (i < n) {
                    x = rl[i];
                    u64 m = mkc[x];
                    if (m != SENT) mask[(unsigned)(m & 0xFFFFFFFFu)] = 1;
                    int c = chase_mk(mkc, euv, x);
                    comp[x] = c;
                    isroot = (c == x);
                }
                int pos = warp_reserve(&g_rcnt[r][b], isroot);
                if (isroot) wl[pos] = x;
            }
            if (r >= 2) {                                // reset consumed buffer
                u64* mkp = g_minkey[(r-1) & 1] + b*VV;
                int n2 = g_rcnt[r-2][b];
                const int* rl2 = g_roots[(r-2) % 3] + b*VV;
                for (int i = gt; i < n2; i += TPB) mkp[rl2[i]] = SENT;
            }
        }
        batch_barrier(b, bar_target);
    }

    // ===== fused compaction: mask -> ascending edge indices (float out) =====
    float* ob = out + (size_t)b * stride;

    // pass 1: count this block's segment
    {
        int s0 = blockIdx.x * SEG;
        int s1 = min(EE, s0 + SEG);
        int cnt = 0;
        for (int i = s0 + tid; i < s1; i += BTH) cnt += mask[i];
        __shared__ int s_red[NW];
        int lane = tid & 31, wid = tid >> 5;
        #pragma unroll
        for (int off = 16; off > 0; off >>= 1) cnt += __shfl_down_sync(0xffffffffu, cnt, off);
        if (lane == 0) s_red[wid] = cnt;
        __syncthreads();
        if (wid == 0) {
            int v = s_red[lane];
            #pragma unroll
            for (int off = 16; off > 0; off >>= 1) v += __shfl_down_sync(0xffffffffu, v, off);
            if (lane == 0) g_bcnt[b*NBLK + blockIdx.x] = v;
        }
    }
    batch_barrier(b, bar_target);

    // block base = exclusive sum over preceding blocks
    __shared__ int s_base;
    if (tid < 32) {
        int v = g_bcnt[b*NBLK + tid];
        int iv = v;
        #pragma unroll
        for (int off = 1; off < 32; off <<= 1) {
            int y = __shfl_up_sync(0xffffffffu, iv, off);
            if (tid >= off) iv += y;
        }
        if (tid == (int)blockIdx.x) s_base = iv - v;
    }
    __syncthreads();

    // pass 2: ordered scatter within segment
    {
        int s0 = blockIdx.x * SEG;
        int s1 = min(EE, s0 + SEG);
        __shared__ int wsum[NW];
        __shared__ int s_run, s_tot;
        if (tid == 0) s_run = s_base;
        __syncthreads();
        int lane = tid & 31, wid = tid >> 5;
        for (int chunk = s0; chunk < s1; chunk += BTH*4) {
            int e0 = chunk + tid*4;
            int m0 = (e0 + 0 < s1) ? mask[e0 + 0] : 0;
            int m1 = (e0 + 1 < s1) ? mask[e0 + 1] : 0;
            int m2 = (e0 + 2 < s1) ? mask[e0 + 2] : 0;
            int m3 = (e0 + 3 < s1) ? mask[e0 + 3] : 0;
            int cnt = m0 + m1 + m2 + m3;
            int inc = cnt;
            #pragma unroll
            for (int off = 1; off < 32; off <<= 1) {
                int y = __shfl_up_sync(0xffffffffu, inc, off);
                if (lane >= off) inc += y;
            }
            if (lane == 31) wsum[wid] = inc;
            __syncthreads();
            if (wid == 0) {
                int v = wsum[lane];
                int iv = v;
                #pragma unroll
                for (int off = 1; off < 32; off <<= 1) {
                    int y = __shfl_up_sync(0xffffffffu, iv, off);
                    if (lane >= off) iv += y;
                }
                wsum[lane] = iv - v;
                if (lane == 31) s_tot = iv;
            }
            __syncthreads();
            int pos = s_run + wsum[wid] + (inc - cnt);
            if (m0) { if (pos < stride) ob[pos] = (float)(e0 + 0); pos++; }
            if (m1) { if (pos < stride) ob[pos] = (float)(e0 + 1); pos++; }
            if (m2) { if (pos < stride) ob[pos] = (float)(e0 + 2); pos++; }
            if (m3) { if (pos < stride) ob[pos] = (float)(e0 + 3); pos++; }
            __syncthreads();
            if (tid == 0) s_run += s_tot;
            __syncthreads();
        }
    }

    // tail fill (padding region, if any)
    if (blockIdx.x == 0) {
        for (int i = NOUT + tid; i < stride; i += BTH) ob[i] = (float)EE;
    }
}

// ---------------- launch ----------------
extern "C" void kernel_launch(void* const* d_in, const int* in_sizes, int n_in,
                              void* d_out, int out_size) {
    const float* fm = (const float*)d_in[0];
    float* out = (float*)d_out;
    (void)in_sizes; (void)n_in;

    int stride = (out_size % BB == 0) ? (out_size / BB) : NOUT;

    dim3 wgrid(WBX, BB);
    dim3 wblk(WQ, WSY);
    weight_kernel<<<wgrid, wblk>>>(fm);

    dim3 pgrid(NBLK, BB);
    boruvka_kernel<<<pgrid, BTH>>>(out, stride);
}

// round 16
// speedup vs baseline: 1.2448x; 1.2448x over previous
#include <cuda_runtime.h>

// ---------------- problem constants (fixed shapes) ----------------
#define BB   4
#define CC   64
#define HH   288
#define WW   432
#define PW   72            // W / TEM
#define TEM_ 6
#define VV   (HH*WW)       // 124416
#define RN   ((HH-1)*PW)   // 20664  vertical edges per phase
#define CN   (HH*(PW-1))   // 20448  horizontal edges per phase
#define XN   (HH*PW)       // 20736  cross edges per phase pair
#define PB   (RN+CN)       // 41112  weight-layout per-phase block
#define EE   (6*RN+6*CN+5*XN) // 350352 total edges
#define NOUT (VV-1)        // 124415 output entries per batch
#define SENT 0xFFFFFFFFFFFFFFFFULL
#define NROUNDS 18

#define NBLK 32                    // blocks per batch (128 total <= 148 SMs -> co-resident)
#define BTH  1024
#define NW   (BTH/32)
#define TPB  (NBLK*BTH)            // threads per batch
// compaction segment per block, rounded UP to a multiple of 4 so uchar4 loads stay aligned
#define SEG  ((((EE + NBLK - 1) / NBLK) + 3) & ~3)

#define NGRP (VV/4)                // 4-pixel groups per batch (31104)

typedef unsigned long long u64;

// ---------------- scratch (device globals; no allocation) ----------------
__device__ u64 g_keys[BB*EE];          // weight-layout key at position e; low 32 = e
__device__ u64 g_minkey[2][BB*VV];     // ping-pong per-round min-key buffers
__device__ u64 g_euv[BB*EE];           // current (cu,cv) of surviving edge e
__device__ int g_comp[BB*VV];
__device__ int g_parent[BB*VV];        // round 0 only
__device__ unsigned char g_mask[BB*EE];
__device__ ulonglong2 g_elist[2][BB*EE];  // {key, (cv<<32)|cu}
__device__ int g_ecnt[NROUNDS][BB];
__device__ int g_rcnt[NROUNDS][BB];
__device__ int g_roots[3][BB*VV];      // 3-deep rotation: need r-2, r-1, r
__device__ unsigned g_barcnt[BB];
__device__ int g_bcnt[BB*NBLK];

// endpoints of edge e in INDEX layout: [rows x6 | cols x6 | cross x5]
__device__ __forceinline__ void edge_uv(int e, int& u, int& v) {
    if (e < 6*RN) {
        int i = e / RN; int j = e - i*RN;
        int r = j / PW;  int c = j - r*PW;
        u = r*WW + i*PW + c; v = u + WW;
    } else if (e < 6*RN + 6*CN) {
        int t = e - 6*RN;
        int i = t / CN; int j = t - i*CN;
        int r = j / (PW-1); int c = j - r*(PW-1);
        u = r*WW + i*PW + c; v = u + 1;
    } else {
        int t = e - 6*RN - 6*CN;
        int i = t / XN; int j = t - i*XN;
        int r = j / PW; int c = j - r*PW;
        u = r*WW + i*PW + c; v = u + PW;
    }
}

__device__ __forceinline__ int chase_root(const int* par, int c) {
    for (int it = 0; it < VV + 2; it++) {
        int p = par[c];
        if (p == c) break;
        int gp = par[p];
        if (gp == c) { c = (c < p) ? c : p; break; }  // 2-cycle: min of pair
        c = p;
    }
    return c;
}

// chase via minkey-derived parents: parent(c) = partner(minkey[c]) or c if SENT
__device__ __forceinline__ int chase_mk(const u64* mk, const u64* euv, int c) {
    u64 m = mk[c];
    for (int it = 0; it < VV + 2; it++) {
        if (m == SENT) return c;                       // c is root
        u64 uv = euv[(unsigned)(m & 0xFFFFFFFFu)];
        int a = (int)(unsigned)(uv & 0xFFFFFFFFu);
        int d = (int)(unsigned)(uv >> 32);
        int p = (a == c) ? d : a;                      // parent(c)
        u64 m2 = mk[p];
        int gp = p;
        if (m2 != SENT) {
            u64 uv2 = euv[(unsigned)(m2 & 0xFFFFFFFFu)];
            int a2 = (int)(unsigned)(uv2 & 0xFFFFFFFFu);
            int d2 = (int)(unsigned)(uv2 >> 32);
            gp = (a2 == p) ? d2 : a2;
        }
        if (gp == c) return (c < p) ? c : p;           // 2-cycle: min of pair
        c = p; m = m2;
    }
    return c;
}

// per-batch grid barrier (all NBLK blocks of batch b co-resident by construction)
__device__ __forceinline__ void batch_barrier(int b, unsigned& target) {
    __syncthreads();
    if (threadIdx.x == 0) {
        __threadfence();
        atomicAdd(&g_barcnt[b], 1u);
        target += NBLK;
        volatile unsigned* p = &g_barcnt[b];
        while (*p < target) { __nanosleep(40); }
        __threadfence();
    }
    __syncthreads();
}

// warp-aggregated append (1 slot per pred); all 32 lanes must call
__device__ __forceinline__ int warp_reserve(int* ctr, bool pred) {
    unsigned ball = __ballot_sync(0xffffffffu, pred);
    int lane = threadIdx.x & 31;
    int total = __popc(ball);
    int base = 0;
    if (lane == 0 && total) base = atomicAdd(ctr, total);
    base = __shfl_sync(0xffffffffu, base, 0);
    return base + __popc(ball & ((1u << lane) - 1u));
}

// warp-aggregated multi-append (cnt in 0..3); all 32 lanes must call
__device__ __forceinline__ int warp_reserve_n(int* ctr, int cnt) {
    int lane = threadIdx.x & 31;
    int inc = cnt;
    #pragma unroll
    for (int off = 1; off < 32; off <<= 1) {
        int y = __shfl_up_sync(0xffffffffu, inc, off);
        if (lane >= off) inc += y;
    }
    int total = __shfl_sync(0xffffffffu, inc, 31);
    int base = 0;
    if (lane == 0 && total) base = atomicAdd(ctr, total);
    base = __shfl_sync(0xffffffffu, base, 0);
    return base + inc - cnt;
}

__device__ __forceinline__ u64 pack_key(float w, int e) {
    return ((u64)__float_as_uint(w) << 32) | (unsigned)e;
}

// ---------------- weights (4 px / thread, float4) + scratch init ----------------
__global__ void __launch_bounds__(256) weight_kernel(const float* __restrict__ fm) {
    int idx = blockIdx.x * blockDim.x + threadIdx.x;
    if (idx >= BB*NGRP) return;
    int b   = idx / NGRP;
    int g   = idx - b*NGRP;
    int pix = g * 4;
    int r   = pix / WW;
    int col = pix - r*WW;
    int ph  = col / PW;
    int c   = col - ph*PW;

    bool hasV  = (r  < HH-1);
    bool hasX  = (ph < TEM_-1);
    bool hasH3 = (c  < PW-4);

    const float* p0 = fm + (size_t)b * CC * VV + pix;
    float sv0=0,sv1=0,sv2=0,sv3=0, sh0=0,sh1=0,sh2=0,sh3=0, sx0=0,sx1=0,sx2=0,sx3=0;

    #pragma unroll 8
    for (int ch = 0; ch < CC; ch++) {
        const float* p = p0 + (size_t)ch * VV;
        float4 x = *reinterpret_cast<const float4*>(p);
        float x4 = hasH3 ? __ldg(p + 4) : 0.f;
        if (hasV) {
            float4 d = *reinterpret_cast<const float4*>(p + WW);
            float t0 = x.x - d.x, t1 = x.y - d.y, t2 = x.z - d.z, t3 = x.w - d.w;
            sv0 += t0*t0; sv1 += t1*t1; sv2 += t2*t2; sv3 += t3*t3;
        }
        {
            float t0 = x.x - x.y, t1 = x.y - x.z, t2 = x.z - x.w, t3 = x.w - x4;
            sh0 += t0*t0; sh1 += t1*t1; sh2 += t2*t2; sh3 += t3*t3;
        }
        if (hasX) {
            float4 d = *reinterpret_cast<const float4*>(p + PW);
            float t0 = x.x - d.x, t1 = x.y - d.y, t2 = x.z - d.z, t3 = x.w - d.w;
            sx0 += t0*t0; sx1 += t1*t1; sx2 += t2*t2; sx3 += t3*t3;
        }
    }

    u64* kb = g_keys + (size_t)b * EE;
    if (hasV) {
        int e = ph*PB + r*PW + c;
        kb[e+0] = pack_key(sv0, e+0); kb[e+1] = pack_key(sv1, e+1);
        kb[e+2] = pack_key(sv2, e+2); kb[e+3] = pack_key(sv3, e+3);
    }
    {
        int e = ph*PB + RN + r*(PW-1) + c;
        kb[e+0] = pack_key(sh0, e+0); kb[e+1] = pack_key(sh1, e+1);
        kb[e+2] = pack_key(sh2, e+2);
        if (hasH3) kb[e+3] = pack_key(sh3, e+3);
    }
    if (hasX) {
        int e = 6*PB + ph*XN + r*PW + c;
        kb[e+0] = pack_key(sx0, e+0); kb[e+1] = pack_key(sx1, e+1);
        kb[e+2] = pack_key(sx2, e+2); kb[e+3] = pack_key(sx3, e+3);
    }

    // ---- fused scratch init ----
    {   // both minkey buffers: 2*BB*VV u64 = 4 ulonglong2 per thread
        ulonglong2 s2 = make_ulonglong2(SENT, SENT);
        ulonglong2* mk = reinterpret_cast<ulonglong2*>(&g_minkey[0][0]) + idx*4;
        mk[0] = s2; mk[1] = s2; mk[2] = s2; mk[3] = s2;
    }
    {
        u64* m8 = reinterpret_cast<u64*>(g_mask);
        for (int i = idx; i < (BB*EE)/8; i += BB*NGRP) m8[i] = 0ULL;
    }
    if (idx < NROUNDS*BB) { (&g_ecnt[0][0])[idx] = 0; (&g_rcnt[0][0])[idx] = 0; }
    if (idx < BB)         g_barcnt[idx] = 0;
    if (idx < BB*NBLK)    g_bcnt[idx] = 0;
}

// ---------------- persistent Boruvka + compaction ----------------
__global__ void __launch_bounds__(BTH, 1) boruvka_kernel(float* __restrict__ out, int stride) {
    int b   = blockIdx.y;
    int tid = threadIdx.x;
    int gt  = blockIdx.x * BTH + tid;
    unsigned bar_target = 0;

    u64* keys   = g_keys + (size_t)b*EE;
    u64* euv    = g_euv  + (size_t)b*EE;
    int* parent = g_parent + b*VV;
    int* comp   = g_comp + b*VV;
    unsigned char* mask = g_mask + (size_t)b*EE;

    // ===== round 0: per-vertex gather over <=6 incident edges (INDEX layout ids) =====
    for (int x = gt; x < VV; x += TPB) {
        int r = x / WW; int col = x - r*WW; int ph = col / PW; int c = col - ph*PW;
        u64 best = SENT;
        u64 k;
        int ev = ph*RN + r*PW + c;                    // vertical
        if (r < HH-1) { k = keys[ev];        if (k < best) best = k; }
        if (r > 0)    { k = keys[ev - PW];   if (k < best) best = k; }
        int eh = 6*RN + ph*CN + r*(PW-1) + c;         // horizontal
        if (c < PW-1) { k = keys[eh];        if (k < best) best = k; }
        if (c > 0)    { k = keys[eh - 1];    if (k < best) best = k; }
        int ex = 6*RN + 6*CN + ph*XN + r*PW + c;      // cross
        if (ph < TEM_-1) { k = keys[ex];      if (k < best) best = k; }
        if (ph > 0)      { k = keys[ex - XN]; if (k < best) best = k; }

        int e = (int)(unsigned)(best & 0xFFFFFFFFu);
        mask[e] = 1;
        int u, v; edge_uv(e, u, v);
        parent[x] = (u == x) ? v : u;
    }
    batch_barrier(b, bar_target);

    // round 0: chase over all V, collect roots -> slot 0
    {
        const int nn = ((VV + TPB - 1) / TPB) * TPB;
        for (int x = gt; x < nn; x += TPB) {
            bool isroot = false;
            if (x < VV) {
                int c = chase_root(parent, x);
                comp[x] = c;
                isroot = (c == x);
            }
            int pos = warp_reserve(&g_rcnt[0][b], isroot);
            if (isroot) g_roots[0][b*VV + pos] = x;
        }
    }
    batch_barrier(b, bar_target);

    // ===== rounds 1..17: [edge | barrier | fused select+chase | barrier] =====
    for (int r = 1; r < NROUNDS; r++) {
        u64* mkc = g_minkey[r & 1] + b*VV;              // written this round

        // ---- edge phase ----
        if (r == 1) {
            // vertex-centric: each vertex reduces its <=6 incident edges, owns 3 appends
            ulonglong2* dst = g_elist[1] + (size_t)b*EE;
            const int nn = ((VV + TPB - 1) / TPB) * TPB;
            for (int x = gt; x < nn; x += TPB) {
                int cnt = 0;
                u64 ak[3], auv[3];
                u64 best = SENT;
                if (x < VV) {
                    int cx = comp[x];
                    int rr = x / WW; int col = x - rr*WW; int ph = col / PW; int c = col - ph*PW;
                    int ev = ph*RN + rr*PW + c;
                    int eh = 6*RN + ph*CN + rr*(PW-1) + c;
                    int ex = 6*RN + 6*CN + ph*XN + rr*PW + c;
                    if (rr < HH-1) {
                        int cn = comp[x + WW];
                        if (cn != cx) {
                            u64 k = keys[ev]; if (k < best) best = k;
                            u64 uv = ((u64)(unsigned)cn << 32) | (unsigned)cx;
                            euv[ev] = uv; ak[cnt] = k; auv[cnt] = uv; cnt++;
                        }
                    }
                    if (rr > 0) {
                        int cn = comp[x - WW];
                        if (cn != cx) { u64 k = keys[ev - PW]; if (k < best) best = k; }
                    }
                    if (c < PW-1) {
                        int cn = comp[x + 1];
                        if (cn != cx) {
                            u64 k = keys[eh]; if (k < best) best = k;
                            u64 uv = ((u64)(unsigned)cn << 32) | (unsigned)cx;
                            euv[eh] = uv; ak[cnt] = k; auv[cnt] = uv; cnt++;
                        }
                    }
                    if (c > 0) {
                        int cn = comp[x - 1];
                        if (cn != cx) { u64 k = keys[eh - 1]; if (k < best) best = k; }
                    }
                    if (ph < TEM_-1) {
                        int cn = comp[x + PW];
                        if (cn != cx) {
                            u64 k = keys[ex]; if (k < best) best = k;
                            u64 uv = ((u64)(unsigned)cn << 32) | (unsigned)cx;
                            euv[ex] = uv; ak[cnt] = k; auv[cnt] = uv; cnt++;
                        }
                    }
                    if (ph > 0) {
                        int cn = comp[x - PW];
                        if (cn != cx) { u64 k = keys[ex - XN]; if (k < best) best = k; }
                    }
                    if (best != SENT) atomicMin(&mkc[cx], best);
                }
                int pos = warp_reserve_n(&g_ecnt[1][b], cnt);
                #pragma unroll
                for (int j = 0; j < 3; j++)
                    if (j < cnt) dst[pos + j] = make_ulonglong2(ak[j], auv[j]);
            }
        } else {
            int n = g_ecnt[r-1][b];
            const ulonglong2* src = g_elist[(r-1) & 1] + (size_t)b*EE;
            ulonglong2* dst = g_elist[r & 1] + (size_t)b*EE;
            int nn = ((n + TPB - 1) / TPB) * TPB;
            for (int i = gt; i < nn; i += TPB) {
                bool pred = false; u64 k = 0, uvp = 0;
                if (i < n) {
                    ulonglong2 ed = src[i];
                    int u = (int)(unsigned)(ed.y & 0xFFFFFFFFu);
                    int v = (int)(unsigned)(ed.y >> 32);
                    int cu = comp[u], cv = comp[v];
                    if (cu != cv) {
                        pred = true;
                        k = ed.x;
                        atomicMin(&mkc[cu], k);
                        atomicMin(&mkc[cv], k);
                        uvp = ((u64)(unsigned)cv << 32) | (unsigned)cu;
                        euv[(unsigned)(k & 0xFFFFFFFFu)] = uvp;
                    }
                }
                int pos = warp_reserve(&g_ecnt[r][b], pred);
                if (pred) dst[pos] = make_ulonglong2(k, uvp);
            }
        }
        batch_barrier(b, bar_target);

        if (g_ecnt[r][b] == 0) break;   // fully merged -> mask complete

        // ---- fused select + chase over roots[r-1]; reset prev minkey over roots[r-2] ----
        {
            int n = g_rcnt[r-1][b];
            const int* rl = g_roots[(r-1) % 3] + b*VV;
            int* wl = g_roots[r % 3] + b*VV;
            int nn = ((n + TPB - 1) / TPB) * TPB;
            for (int i = gt; i < nn; i += TPB) {
                bool isroot = false;
                int x = 0;
                if (i < n) {
                    x = rl[i];
                    u64 m = mkc[x];
                    if (m != SENT) mask[(unsigned)(m & 0xFFFFFFFFu)] = 1;
                    int c = chase_mk(mkc, euv, x);
                    comp[x] = c;
                    isroot = (c == x);
                }
                int pos = warp_reserve(&g_rcnt[r][b], isroot);
                if (isroot) wl[pos] = x;
            }
            if (r >= 2) {                                // reset consumed buffer
                u64* mkp = g_minkey[(r-1) & 1] + b*VV;
                int n2 = g_rcnt[r-2][b];
                const int* rl2 = g_roots[(r-2) % 3] + b*VV;
                for (int i = gt; i < n2; i += TPB) mkp[rl2[i]] = SENT;
            }
        }
        batch_barrier(b, bar_target);
    }

    // ===== fused compaction: mask -> ascending edge indices (float out) =====
    float* ob = out + (size_t)b * stride;

    // pass 1: count this block's segment
    {
        int s0 = blockIdx.x * SEG;
        int s1 = min(EE, s0 + SEG);
        int cnt = 0;
        for (int i = s0 + tid; i < s1; i += BTH) cnt += mask[i];
        __shared__ int s_red[NW];
        int lane = tid & 31, wid = tid >> 5;
        #pragma unroll
        for (int off = 16; off > 0; off >>= 1) cnt += __shfl_down_sync(0xffffffffu, cnt, off);
        if (lane == 0) s_red[wid] = cnt;
        __syncthreads();
        if (wid == 0) {
            int v = s_red[lane];
            #pragma unroll
            for (int off = 16; off > 0; off >>= 1) v += __shfl_down_sync(0xffffffffu, v, off);
            if (lane == 0) g_bcnt[b*NBLK + blockIdx.x] = v;
        }
    }
    batch_barrier(b, bar_target);

    // block base = exclusive sum over preceding blocks
    __shared__ int s_base;
    if (tid < 32) {
        int v = g_bcnt[b*NBLK + tid];
        int iv = v;
        #pragma unroll
        for (int off = 1; off < 32; off <<= 1) {
            int y = __shfl_up_sync(0xffffffffu, iv, off);
            if (tid >= off) iv += y;
        }
        if (tid == (int)blockIdx.x) s_base = iv - v;
    }
    __syncthreads();

    // pass 2: ordered scatter within segment (uchar4 loads; SEG multiple of 4)
    {
        int s0 = blockIdx.x * SEG;
        int s1 = min(EE, s0 + SEG);
        __shared__ int wsum[NW];
        __shared__ int s_run, s_tot;
        if (tid == 0) s_run = s_base;
        __syncthreads();
        int lane = tid & 31, wid = tid >> 5;
        for (int chunk = s0; chunk < s1; chunk += BTH*4) {
            int e0 = chunk + tid*4;
            int m0 = 0, m1 = 0, m2 = 0, m3 = 0;
            if (e0 + 3 < s1) {
                uchar4 mv = *reinterpret_cast<const uchar4*>(mask + e0);
                m0 = mv.x; m1 = mv.y; m2 = mv.z; m3 = mv.w;
            } else {
                m0 = (e0 + 0 < s1) ? mask[e0 + 0] : 0;
                m1 = (e0 + 1 < s1) ? mask[e0 + 1] : 0;
                m2 = (e0 + 2 < s1) ? mask[e0 + 2] : 0;
                m3 = (e0 + 3 < s1) ? mask[e0 + 3] : 0;
            }
            int cnt = m0 + m1 + m2 + m3;
            int inc = cnt;
            #pragma unroll
            for (int off = 1; off < 32; off <<= 1) {
                int y = __shfl_up_sync(0xffffffffu, inc, off);
                if (lane >= off) inc += y;
            }
            if (lane == 31) wsum[wid] = inc;
            __syncthreads();
            if (wid == 0) {
                int v = wsum[lane];
                int iv = v;
                #pragma unroll
                for (int off = 1; off < 32; off <<= 1) {
                    int y = __shfl_up_sync(0xffffffffu, iv, off);
                    if (lane >= off) iv += y;
                }
                wsum[lane] = iv - v;
                if (lane == 31) s_tot = iv;
            }
            __syncthreads();
            int pos = s_run + wsum[wid] + (inc - cnt);
            if (m0) { if (pos < stride) ob[pos] = (float)(e0 + 0); pos++; }
            if (m1) { if (pos < stride) ob[pos] = (float)(e0 + 1); pos++; }
            if (m2) { if (pos < stride) ob[pos] = (float)(e0 + 2); pos++; }
            if (m3) { if (pos < stride) ob[pos] = (float)(e0 + 3); pos++; }
            __syncthreads();
            if (tid == 0) s_run += s_tot;
            __syncthreads();
        }
    }

    // tail fill (padding region, if any)
    if (blockIdx.x == 0) {
        for (int i = NOUT + tid; i < stride; i += BTH) ob[i] = (float)EE;
    }
}

// ---------------- launch ----------------
extern "C" void kernel_launch(void* const* d_in, const int* in_sizes, int n_in,
                              void* d_out, int out_size) {
    const float* fm = (const float*)d_in[0];
    float* out = (float*)d_out;
    (void)in_sizes; (void)n_in;

    int stride = (out_size % BB == 0) ? (out_size / BB) : NOUT;

    weight_kernel<<<(BB*NGRP + 255) / 256, 256>>>(fm);

    dim3 pgrid(NBLK, BB);
    boruvka_kernel<<<pgrid, BTH>>>(out, stride);
}

// round 17
// speedup vs baseline: 1.2522x; 1.0059x over previous
#include <cuda_runtime.h>

// ---------------- problem constants (fixed shapes) ----------------
#define BB   4
#define CC   64
#define HH   288
#define WW   432
#define PW   72            // W / TEM
#define TEM_ 6
#define VV   (HH*WW)       // 124416
#define RN   ((HH-1)*PW)   // 20664  vertical edges per phase
#define CN   (HH*(PW-1))   // 20448  horizontal edges per phase
#define XN   (HH*PW)       // 20736  cross edges per phase pair
#define PB   (RN+CN)       // 41112  weight-layout per-phase block
#define EE   (6*RN+6*CN+5*XN) // 350352 total edges
#define NOUT (VV-1)        // 124415 output entries per batch
#define SENT 0xFFFFFFFFFFFFFFFFULL
#define NROUNDS 18

#define NBLK 32                    // blocks per batch (128 total <= 148 SMs -> co-resident)
#define BTH  1024
#define NW   (BTH/32)
#define TPB  (NBLK*BTH)            // threads per batch
// compaction segment per block, rounded UP to a multiple of 4 so uchar4 loads stay aligned
#define SEG  ((((EE + NBLK - 1) / NBLK) + 3) & ~3)

#define NGRP (VV/4)                // 4-pixel groups per batch (31104)

typedef unsigned long long u64;

// ---------------- scratch (device globals; no allocation) ----------------
__device__ u64 g_keys[BB*EE];          // weight-layout key at position e; low 32 = e
__device__ u64 g_minkey[2][BB*VV];     // ping-pong per-round min-key buffers
__device__ u64 g_euv[BB*EE];           // current (cu,cv) of surviving edge e
__device__ int g_comp[BB*VV];
__device__ int g_parent[BB*VV];        // round 0 only
__device__ unsigned char g_mask[BB*EE];
__device__ ulonglong2 g_elist[2][BB*EE];  // {key, (cv<<32)|cu}
__device__ int g_ecnt[NROUNDS][BB];
__device__ int g_rcnt[NROUNDS][BB];
__device__ int g_roots[3][BB*VV];      // 3-deep rotation: need r-2, r-1, r
__device__ unsigned g_barcnt[BB];
__device__ int g_bcnt[BB*NBLK];        // written before read every launch; no reset needed

// endpoints of edge e in INDEX layout: [rows x6 | cols x6 | cross x5]
__device__ __forceinline__ void edge_uv(int e, int& u, int& v) {
    if (e < 6*RN) {
        int i = e / RN; int j = e - i*RN;
        int r = j / PW;  int c = j - r*PW;
        u = r*WW + i*PW + c; v = u + WW;
    } else if (e < 6*RN + 6*CN) {
        int t = e - 6*RN;
        int i = t / CN; int j = t - i*CN;
        int r = j / (PW-1); int c = j - r*(PW-1);
        u = r*WW + i*PW + c; v = u + 1;
    } else {
        int t = e - 6*RN - 6*CN;
        int i = t / XN; int j = t - i*XN;
        int r = j / PW; int c = j - r*PW;
        u = r*WW + i*PW + c; v = u + PW;
    }
}

__device__ __forceinline__ int chase_root(const int* par, int c) {
    for (int it = 0; it < VV + 2; it++) {
        int p = par[c];
        if (p == c) break;
        int gp = par[p];
        if (gp == c) { c = (c < p) ? c : p; break; }  // 2-cycle: min of pair
        c = p;
    }
    return c;
}

// chase via minkey-derived parents: parent(c) = partner(minkey[c]) or c if SENT
__device__ __forceinline__ int chase_mk(const u64* mk, const u64* euv, int c) {
    u64 m = mk[c];
    for (int it = 0; it < VV + 2; it++) {
        if (m == SENT) return c;                       // c is root
        u64 uv = euv[(unsigned)(m & 0xFFFFFFFFu)];
        int a = (int)(unsigned)(uv & 0xFFFFFFFFu);
        int d = (int)(unsigned)(uv >> 32);
        int p = (a == c) ? d : a;                      // parent(c)
        u64 m2 = mk[p];
        int gp = p;
        if (m2 != SENT) {
            u64 uv2 = euv[(unsigned)(m2 & 0xFFFFFFFFu)];
            int a2 = (int)(unsigned)(uv2 & 0xFFFFFFFFu);
            int d2 = (int)(unsigned)(uv2 >> 32);
            gp = (a2 == p) ? d2 : a2;
        }
        if (gp == c) return (c < p) ? c : p;           // 2-cycle: min of pair
        c = p; m = m2;
    }
    return c;
}

// per-batch grid barrier (all NBLK blocks of batch b co-resident by construction)
__device__ __forceinline__ void batch_barrier(int b, unsigned& target) {
    __syncthreads();
    if (threadIdx.x == 0) {
        __threadfence();
        atomicAdd(&g_barcnt[b], 1u);
        target += NBLK;
        volatile unsigned* p = &g_barcnt[b];
        while (*p < target) { __nanosleep(40); }
        __threadfence();
    }
    __syncthreads();
}

// warp-aggregated append (1 slot per pred); all 32 lanes must call
__device__ __forceinline__ int warp_reserve(int* ctr, bool pred) {
    unsigned ball = __ballot_sync(0xffffffffu, pred);
    int lane = threadIdx.x & 31;
    int total = __popc(ball);
    int base = 0;
    if (lane == 0 && total) base = atomicAdd(ctr, total);
    base = __shfl_sync(0xffffffffu, base, 0);
    return base + __popc(ball & ((1u << lane) - 1u));
}

// warp-aggregated multi-append (cnt in 0..3); all 32 lanes must call
__device__ __forceinline__ int warp_reserve_n(int* ctr, int cnt) {
    int lane = threadIdx.x & 31;
    int inc = cnt;
    #pragma unroll
    for (int off = 1; off < 32; off <<= 1) {
        int y = __shfl_up_sync(0xffffffffu, inc, off);
        if (lane >= off) inc += y;
    }
    int total = __shfl_sync(0xffffffffu, inc, 31);
    int base = 0;
    if (lane == 0 && total) base = atomicAdd(ctr, total);
    base = __shfl_sync(0xffffffffu, base, 0);
    return base + inc - cnt;
}

__device__ __forceinline__ u64 pack_key(float w, int e) {
    return ((u64)__float_as_uint(w) << 32) | (unsigned)e;
}

// ---------------- tiny reset: barrier + append counters (must precede main kernel) ----
__global__ void reset_kernel() {
    int t = threadIdx.x;
    if (t < BB) g_barcnt[t] = 0;
    if (t < NROUNDS*BB) { (&g_ecnt[0][0])[t] = 0; (&g_rcnt[0][0])[t] = 0; }
}

// ---------------- fused: weights + init + persistent Boruvka + compaction ----------------
__global__ void __launch_bounds__(BTH, 1) boruvka_kernel(const float* __restrict__ fm,
                                                         float* __restrict__ out, int stride) {
    int b   = blockIdx.y;
    int tid = threadIdx.x;
    int gt  = blockIdx.x * BTH + tid;
    unsigned bar_target = 0;

    u64* keys   = g_keys + (size_t)b*EE;
    u64* euv    = g_euv  + (size_t)b*EE;
    int* parent = g_parent + b*VV;
    int* comp   = g_comp + b*VV;
    unsigned char* mask = g_mask + (size_t)b*EE;

    // ===== phase 0: weights (4 px / thread) + per-batch scratch init =====
    if (gt < NGRP) {
        int g   = gt;
        int pix = g * 4;
        int r   = pix / WW;
        int col = pix - r*WW;
        int ph  = col / PW;
        int c   = col - ph*PW;

        bool hasV  = (r  < HH-1);
        bool hasX  = (ph < TEM_-1);
        bool hasH3 = (c  < PW-4);

        const float* p0 = fm + (size_t)b * CC * VV + pix;
        float sv0=0,sv1=0,sv2=0,sv3=0, sh0=0,sh1=0,sh2=0,sh3=0, sx0=0,sx1=0,sx2=0,sx3=0;

        #pragma unroll 8
        for (int ch = 0; ch < CC; ch++) {
            const float* p = p0 + (size_t)ch * VV;
            float4 x = *reinterpret_cast<const float4*>(p);
            float x4 = hasH3 ? __ldg(p + 4) : 0.f;
            if (hasV) {
                float4 d = *reinterpret_cast<const float4*>(p + WW);
                float t0 = x.x - d.x, t1 = x.y - d.y, t2 = x.z - d.z, t3 = x.w - d.w;
                sv0 += t0*t0; sv1 += t1*t1; sv2 += t2*t2; sv3 += t3*t3;
            }
            {
                float t0 = x.x - x.y, t1 = x.y - x.z, t2 = x.z - x.w, t3 = x.w - x4;
                sh0 += t0*t0; sh1 += t1*t1; sh2 += t2*t2; sh3 += t3*t3;
            }
            if (hasX) {
                float4 d = *reinterpret_cast<const float4*>(p + PW);
                float t0 = x.x - d.x, t1 = x.y - d.y, t2 = x.z - d.z, t3 = x.w - d.w;
                sx0 += t0*t0; sx1 += t1*t1; sx2 += t2*t2; sx3 += t3*t3;
            }
        }

        if (hasV) {
            int e = ph*PB + r*PW + c;
            keys[e+0] = pack_key(sv0, e+0); keys[e+1] = pack_key(sv1, e+1);
            keys[e+2] = pack_key(sv2, e+2); keys[e+3] = pack_key(sv3, e+3);
        }
        {
            int e = ph*PB + RN + r*(PW-1) + c;
            keys[e+0] = pack_key(sh0, e+0); keys[e+1] = pack_key(sh1, e+1);
            keys[e+2] = pack_key(sh2, e+2);
            if (hasH3) keys[e+3] = pack_key(sh3, e+3);
        }
        if (hasX) {
            int e = 6*PB + ph*XN + r*PW + c;
            keys[e+0] = pack_key(sx0, e+0); keys[e+1] = pack_key(sx1, e+1);
            keys[e+2] = pack_key(sx2, e+2); keys[e+3] = pack_key(sx3, e+3);
        }
    }
    // per-batch scratch init (both minkey buffers + mask), by this batch's blocks
    {
        ulonglong2 s2 = make_ulonglong2(SENT, SENT);
        ulonglong2* mk0 = reinterpret_cast<ulonglong2*>(g_minkey[0] + b*VV);
        ulonglong2* mk1 = reinterpret_cast<ulonglong2*>(g_minkey[1] + b*VV);
        for (int i = gt; i < VV/2; i += TPB) { mk0[i] = s2; mk1[i] = s2; }
        u64* m8 = reinterpret_cast<u64*>(g_mask + (size_t)b*EE);
        for (int i = gt; i < EE/8; i += TPB) m8[i] = 0ULL;
    }
    batch_barrier(b, bar_target);

    // ===== round 0: per-vertex gather over <=6 incident edges (INDEX layout ids) =====
    for (int x = gt; x < VV; x += TPB) {
        int r = x / WW; int col = x - r*WW; int ph = col / PW; int c = col - ph*PW;
        u64 best = SENT;
        u64 k;
        int ev = ph*RN + r*PW + c;                    // vertical
        if (r < HH-1) { k = keys[ev];        if (k < best) best = k; }
        if (r > 0)    { k = keys[ev - PW];   if (k < best) best = k; }
        int eh = 6*RN + ph*CN + r*(PW-1) + c;         // horizontal
        if (c < PW-1) { k = keys[eh];        if (k < best) best = k; }
        if (c > 0)    { k = keys[eh - 1];    if (k < best) best = k; }
        int ex = 6*RN + 6*CN + ph*XN + r*PW + c;      // cross
        if (ph < TEM_-1) { k = keys[ex];      if (k < best) best = k; }
        if (ph > 0)      { k = keys[ex - XN]; if (k < best) best = k; }

        int e = (int)(unsigned)(best & 0xFFFFFFFFu);
        mask[e] = 1;
        int u, v; edge_uv(e, u, v);
        parent[x] = (u == x) ? v : u;
    }
    batch_barrier(b, bar_target);

    // round 0: chase over all V, collect roots -> slot 0
    {
        const int nn = ((VV + TPB - 1) / TPB) * TPB;
        for (int x = gt; x < nn; x += TPB) {
            bool isroot = false;
            if (x < VV) {
                int c = chase_root(parent, x);
                comp[x] = c;
                isroot = (c == x);
            }
            int pos = warp_reserve(&g_rcnt[0][b], isroot);
            if (isroot) g_roots[0][b*VV + pos] = x;
        }
    }
    batch_barrier(b, bar_target);

    // ===== rounds 1..17: [edge | barrier | fused select+chase | barrier] =====
    for (int r = 1; r < NROUNDS; r++) {
        u64* mkc = g_minkey[r & 1] + b*VV;              // written this round

        // ---- edge phase ----
        if (r == 1) {
            // vertex-centric: each vertex reduces its <=6 incident edges, owns 3 appends
            ulonglong2* dst = g_elist[1] + (size_t)b*EE;
            const int nn = ((VV + TPB - 1) / TPB) * TPB;
            for (int x = gt; x < nn; x += TPB) {
                int cnt = 0;
                u64 ak[3], auv[3];
                u64 best = SENT;
                if (x < VV) {
                    int cx = comp[x];
                    int rr = x / WW; int col = x - rr*WW; int ph = col / PW; int c = col - ph*PW;
                    int ev = ph*RN + rr*PW + c;
                    int eh = 6*RN + ph*CN + rr*(PW-1) + c;
                    int ex = 6*RN + 6*CN + ph*XN + rr*PW + c;
                    if (rr < HH-1) {
                        int cn = comp[x + WW];
                        if (cn != cx) {
                            u64 k = keys[ev]; if (k < best) best = k;
                            u64 uv = ((u64)(unsigned)cn << 32) | (unsigned)cx;
                            euv[ev] = uv; ak[cnt] = k; auv[cnt] = uv; cnt++;
                        }
                    }
                    if (rr > 0) {
                        int cn = comp[x - WW];
                        if (cn != cx) { u64 k = keys[ev - PW]; if (k < best) best = k; }
                    }
                    if (c < PW-1) {
                        int cn = comp[x + 1];
                        if (cn != cx) {
                            u64 k = keys[eh]; if (k < best) best = k;
                            u64 uv = ((u64)(unsigned)cn << 32) | (unsigned)cx;
                            euv[eh] = uv; ak[cnt] = k; auv[cnt] = uv; cnt++;
                        }
                    }
                    if (c > 0) {
                        int cn = comp[x - 1];
                        if (cn != cx) { u64 k = keys[eh - 1]; if (k < best) best = k; }
                    }
                    if (ph < TEM_-1) {
                        int cn = comp[x + PW];
                        if (cn != cx) {
                            u64 k = keys[ex]; if (k < best) best = k;
                            u64 uv = ((u64)(unsigned)cn << 32) | (unsigned)cx;
                            euv[ex] = uv; ak[cnt] = k; auv[cnt] = uv; cnt++;
                        }
                    }
                    if (ph > 0) {
                        int cn = comp[x - PW];
                        if (cn != cx) { u64 k = keys[ex - XN]; if (k < best) best = k; }
                    }
                    if (best != SENT) atomicMin(&mkc[cx], best);
                }
                int pos = warp_reserve_n(&g_ecnt[1][b], cnt);
                #pragma unroll
                for (int j = 0; j < 3; j++)
                    if (j < cnt) dst[pos + j] = make_ulonglong2(ak[j], auv[j]);
            }
        } else {
            int n = g_ecnt[r-1][b];
            const ulonglong2* src = g_elist[(r-1) & 1] + (size_t)b*EE;
            ulonglong2* dst = g_elist[r & 1] + (size_t)b*EE;
            int nn = ((n + TPB - 1) / TPB) * TPB;
            for (int i = gt; i < nn; i += TPB) {
                bool pred = false; u64 k = 0, uvp = 0;
                if (i < n) {
                    ulonglong2 ed = src[i];
                    int u = (int)(unsigned)(ed.y & 0xFFFFFFFFu);
                    int v = (int)(unsigned)(ed.y >> 32);
                    int cu = comp[u], cv = comp[v];
                    if (cu != cv) {
                        pred = true;
                        k = ed.x;
                        atomicMin(&mkc[cu], k);
                        atomicMin(&mkc[cv], k);
                        uvp = ((u64)(unsigned)cv << 32) | (unsigned)cu;
                        euv[(unsigned)(k & 0xFFFFFFFFu)] = uvp;
                    }
                }
                int pos = warp_reserve(&g_ecnt[r][b], pred);
                if (pred) dst[pos] = make_ulonglong2(k, uvp);
            }
        }
        batch_barrier(b, bar_target);

        if (g_ecnt[r][b] == 0) break;   // fully merged -> mask complete

        // ---- fused select + chase over roots[r-1]; reset prev minkey over roots[r-2] ----
        {
            int n = g_rcnt[r-1][b];
            const int* rl = g_roots[(r-1) % 3] + b*VV;
            int* wl = g_roots[r % 3] + b*VV;
            int nn = ((n + TPB - 1) / TPB) * TPB;
            for (int i = gt; i < nn; i += TPB) {
                bool isroot = false;
                int x = 0;
                if (i < n) {
                    x = rl[i];
                    u64 m = mkc[x];
                    if (m != SENT) mask[(unsigned)(m & 0xFFFFFFFFu)] = 1;
                    int c = chase_mk(mkc, euv, x);
                    comp[x] = c;
                    isroot = (c == x);
                }
                int pos = warp_reserve(&g_rcnt[r][b], isroot);
                if (isroot) wl[pos] = x;
            }
            if (r >= 2) {                                // reset consumed buffer
                u64* mkp = g_minkey[(r-1) & 1] + b*VV;
                int n2 = g_rcnt[r-2][b];
                const int* rl2 = g_roots[(r-2) % 3] + b*VV;
                for (int i = gt; i < n2; i += TPB) mkp[rl2[i]] = SENT;
            }
        }
        batch_barrier(b, bar_target);
    }

    // ===== fused compaction: mask -> ascending edge indices (float out) =====
    float* ob = out + (size_t)b * stride;

    // pass 1: count this block's segment
    {
        int s0 = blockIdx.x * SEG;
        int s1 = min(EE, s0 + SEG);
        int cnt = 0;
        for (int i = s0 + tid; i < s1; i += BTH) cnt += mask[i];
        __shared__ int s_red[NW];
        int lane = tid & 31, wid = tid >> 5;
        #pragma unroll
        for (int off = 16; off > 0; off >>= 1) cnt += __shfl_down_sync(0xffffffffu, cnt, off);
        if (lane == 0) s_red[wid] = cnt;
        __syncthreads();
        if (wid == 0) {
            int v = s_red[lane];
            #pragma unroll
            for (int off = 16; off > 0; off >>= 1) v += __shfl_down_sync(0xffffffffu, v, off);
            if (lane == 0) g_bcnt[b*NBLK + blockIdx.x] = v;
        }
    }
    batch_barrier(b, bar_target);

    // block base = exclusive sum over preceding blocks
    __shared__ int s_base;
    if (tid < 32) {
        int v = g_bcnt[b*NBLK + tid];
        int iv = v;
        #pragma unroll
        for (int off = 1; off < 32; off <<= 1) {
            int y = __shfl_up_sync(0xffffffffu, iv, off);
            if (tid >= off) iv += y;
        }
        if (tid == (int)blockIdx.x) s_base = iv - v;
    }
    __syncthreads();

    // pass 2: ordered scatter within segment (uchar4 loads; SEG multiple of 4)
    {
        int s0 = blockIdx.x * SEG;
        int s1 = min(EE, s0 + SEG);
        __shared__ int wsum[NW];
        __shared__ int s_run, s_tot;
        if (tid == 0) s_run = s_base;
        __syncthreads();
        int lane = tid & 31, wid = tid >> 5;
        for (int chunk = s0; chunk < s1; chunk += BTH*4) {
            int e0 = chunk + tid*4;
            int m0 = 0, m1 = 0, m2 = 0, m3 = 0;
            if (e0 + 3 < s1) {
                uchar4 mv = *reinterpret_cast<const uchar4*>(mask + e0);
                m0 = mv.x; m1 = mv.y; m2 = mv.z; m3 = mv.w;
            } else {
                m0 = (e0 + 0 < s1) ? mask[e0 + 0] : 0;
                m1 = (e0 + 1 < s1) ? mask[e0 + 1] : 0;
                m2 = (e0 + 2 < s1) ? mask[e0 + 2] : 0;
                m3 = (e0 + 3 < s1) ? mask[e0 + 3] : 0;
            }
            int cnt = m0 + m1 + m2 + m3;
            int inc = cnt;
            #pragma unroll
            for (int off = 1; off < 32; off <<= 1) {
                int y = __shfl_up_sync(0xffffffffu, inc, off);
                if (lane >= off) inc += y;
            }
            if (lane == 31) wsum[wid] = inc;
            __syncthreads();
            if (wid == 0) {
                int v = wsum[lane];
                int iv = v;
                #pragma unroll
                for (int off = 1; off < 32; off <<= 1) {
                    int y = __shfl_up_sync(0xffffffffu, iv, off);
                    if (lane >= off) iv += y;
                }
                wsum[lane] = iv - v;
                if (lane == 31) s_tot = iv;
            }
            __syncthreads();
            int pos = s_run + wsum[wid] + (inc - cnt);
            if (m0) { if (pos < stride) ob[pos] = (float)(e0 + 0); pos++; }
            if (m1) { if (pos < stride) ob[pos] = (float)(e0 + 1); pos++; }
            if (m2) { if (pos < stride) ob[pos] = (float)(e0 + 2); pos++; }
            if (m3) { if (pos < stride) ob[pos] = (float)(e0 + 3); pos++; }
            __syncthreads();
            if (tid == 0) s_run += s_tot;
            __syncthreads();
        }
    }

    // tail fill (padding region, if any)
    if (blockIdx.x == 0) {
        for (int i = NOUT + tid; i < stride; i += BTH) ob[i] = (float)EE;
    }
}

// ---------------- launch ----------------
extern "C" void kernel_launch(void* const* d_in, const int* in_sizes, int n_in,
                              void* d_out, int out_size) {
    const float* fm = (const float*)d_in[0];
    float* out = (float*)d_out;
    (void)in_sizes; (void)n_in;

    int stride = (out_size % BB == 0) ? (out_size / BB) : NOUT;

    reset_kernel<<<1, 128>>>();

    dim3 pgrid(NBLK, BB);
    boruvka_kernel<<<pgrid, BTH>>>(fm, out, stride);
}